// round 4
// baseline (speedup 1.0000x reference)
#include <cuda_runtime.h>
#include <math.h>

// ---------------- problem constants ----------------
#define CB   8
#define CT   24
#define CW   48
#define CD   512
#define CH   8
#define CE   64
#define CDI  1024
#define CS   64
#define CR   32
#define CKC  4
#define CDFF 2048
#define CL   1152          // T*W
#define CM   9216          // B*L

// ---------------- scratch (device globals; no cudaMalloc allowed) ----------------
__device__ float g_q[CM * CD];
__device__ float g_k[CM * CD];
__device__ float g_v[CM * CD];
__device__ float g_scores[(size_t)CB * CH * CL * CL];   // 340 MB, reused as probs
__device__ float g_attn[CM * CD];
__device__ float g_xattn[CM * CD];
__device__ float g_xz[CM * 2 * CDI];
__device__ float g_uact[CM * CDI];
__device__ float g_xdbc[CM * (CR + 2 * CS)];
__device__ float g_delta[CM * CDI];
__device__ float g_yss[CM * CDI];
__device__ float g_mamba[CM * CD];
__device__ float g_h[CM * CD];
__device__ float g_hn[CM * CD];
__device__ float g_ff1[CM * CDFF];

// ---------------- reductions ----------------
__device__ __forceinline__ float warpSum(float v) {
    #pragma unroll
    for (int o = 16; o; o >>= 1) v += __shfl_xor_sync(0xffffffffu, v, o);
    return v;
}
__device__ __forceinline__ float warpMax(float v) {
    #pragma unroll
    for (int o = 16; o; o >>= 1) v = fmaxf(v, __shfl_xor_sync(0xffffffffu, v, o));
    return v;
}
__device__ float blockSum(float v) {
    __shared__ float sh[32];
    int lane = threadIdx.x & 31, wid = threadIdx.x >> 5;
    v = warpSum(v);
    if (lane == 0) sh[wid] = v;
    __syncthreads();
    int nw = blockDim.x >> 5;
    v = (threadIdx.x < nw) ? sh[threadIdx.x] : 0.f;
    if (wid == 0) v = warpSum(v);
    if (threadIdx.x == 0) sh[0] = v;
    __syncthreads();
    float r = sh[0];
    __syncthreads();
    return r;
}
__device__ float blockMax(float v) {
    __shared__ float sh[32];
    int lane = threadIdx.x & 31, wid = threadIdx.x >> 5;
    v = warpMax(v);
    if (lane == 0) sh[wid] = v;
    __syncthreads();
    int nw = blockDim.x >> 5;
    v = (threadIdx.x < nw) ? sh[threadIdx.x] : -INFINITY;
    if (wid == 0) v = warpMax(v);
    if (threadIdx.x == 0) sh[0] = v;
    __syncthreads();
    float r = sh[0];
    __syncthreads();
    return r;
}

// ---------------- tf32 helpers ----------------
__device__ __forceinline__ unsigned f2tf(float f) {
    unsigned u;
    asm("cvt.rna.tf32.f32 %0, %1;" : "=r"(u) : "f"(f));
    return u;
}
__device__ __forceinline__ void mma8(float* c, const unsigned* a, const unsigned* b) {
    asm volatile("mma.sync.aligned.m16n8k8.row.col.f32.tf32.tf32.f32 "
                 "{%0,%1,%2,%3}, {%4,%5,%6,%7}, {%8,%9}, {%0,%1,%2,%3};\n"
                 : "+f"(c[0]), "+f"(c[1]), "+f"(c[2]), "+f"(c[3])
                 : "r"(a[0]), "r"(a[1]), "r"(a[2]), "r"(a[3]),
                   "r"(b[0]), "r"(b[1]));
}
__device__ __forceinline__ void cpasync16(unsigned saddr, const void* gptr, int srcsz) {
    asm volatile("cp.async.cg.shared.global [%0], [%1], 16, %2;"
                 :: "r"(saddr), "l"(gptr), "r"(srcsz));
}
#define CP_COMMIT() asm volatile("cp.async.commit_group;")
#define CP_WAIT(n)  asm volatile("cp.async.wait_group %0;" :: "n"(n))

// ================= pipelined tf32 GEMM (TB=1: C = A * B^T, both K-contiguous) =======
// 128x128 CTA tile, BK=16, 3-stage cp.async pipeline, 256 threads (8 warps).
// M % 128 == 0, K % 16 == 0 (all call sites). N edge handled via cp.async zfill +
// epilogue guards. EPI: 0 none, 1 exact GELU, 2 softplus. Batched over blockIdx.z.
template <int EPI>
__global__ __launch_bounds__(256, 2)
void tgemm2_kernel(const float* __restrict__ A, const float* __restrict__ Bm,
                   const float* __restrict__ bias, const float* __restrict__ resid,
                   float* __restrict__ C,
                   int M, int N, int K, int lda, int ldb, int ldc,
                   int zdiv, long long sA1, long long sA2,
                   long long sB1, long long sB2,
                   long long sC1, long long sC2) {
    constexpr int ST = 3;
    constexpr int TW = 128 * 16;                 // words per tile stage
    __shared__ float As[ST * TW];
    __shared__ float Bs[ST * TW];

    int z = blockIdx.z;
    int zq = z / zdiv, zr = z - zq * zdiv;
    A += zq * sA1 + (long long)zr * sA2;
    Bm += zq * sB1 + (long long)zr * sB2;
    C += zq * sC1 + (long long)zr * sC2;
    const float* Rp = resid ? (resid + zq * sC1 + (long long)zr * sC2) : nullptr;

    const int m0 = blockIdx.y * 128, n0 = blockIdx.x * 128;
    const int tid = threadIdx.x;
    const int lane = tid & 31, warp = tid >> 5;
    const int grp = lane >> 2, tig = lane & 3;
    const int wm0 = (warp & 3) * 32;
    const int wn0 = (warp >> 2) * 64;

    // ---- loader setup: each thread copies 2 A-chunks + 2 B-chunks (16B) per tile ----
    const int q = tid & 3;
    const int r0l = tid >> 2;                    // 0..63
    unsigned aW[2], bW[2];                       // smem byte offsets within a stage
    const float* Ag[2]; const float* Bg[2]; int bsz[2];
    unsigned asb = (unsigned)__cvta_generic_to_shared(As);
    unsigned bsb = (unsigned)__cvta_generic_to_shared(Bs);
    #pragma unroll
    for (int i = 0; i < 2; i++) {
        int r = r0l + i * 64;
        unsigned w = (unsigned)(r * 16 + 4 * (q ^ ((r >> 1) & 3)));
        aW[i] = w * 4; bW[i] = w * 4;
        Ag[i] = A + (long long)(m0 + r) * lda + 4 * q;
        int bn = n0 + r;
        int bcl = bn < N ? bn : (N - 1);
        Bg[i] = Bm + (long long)bcl * ldb + 4 * q;
        bsz[i] = (bn < N) ? 16 : 0;
    }
    const int T = K / 16;
    auto issue = [&](int t) {
        if (t < T) {
            int s = t - (t / ST) * ST;
            unsigned ab = asb + s * (TW * 4), bb = bsb + s * (TW * 4);
            #pragma unroll
            for (int i = 0; i < 2; i++) {
                cpasync16(ab + aW[i], Ag[i] + t * 16, 16);
                cpasync16(bb + bW[i], Bg[i] + t * 16, bsz[i]);
            }
        }
        CP_COMMIT();
    };

    // ---- fragment address setup (hoisted; swizzle index invariant per thread) ----
    const int sA_swz = ((wm0 + grp) >> 1) & 3;
    const int sB_swz = ((wn0 + grp) >> 1) & 3;
    int colA[4], colB[4];
    #pragma unroll
    for (int qq = 0; qq < 4; qq++) {
        colA[qq] = tig + 4 * (qq ^ sA_swz);
        colB[qq] = tig + 4 * (qq ^ sB_swz);
    }

    float c[2][8][4];
    #pragma unroll
    for (int mi = 0; mi < 2; mi++)
        #pragma unroll
        for (int ni = 0; ni < 8; ni++)
            #pragma unroll
            for (int j = 0; j < 4; j++) c[mi][ni][j] = 0.f;

    issue(0); issue(1);

    for (int t = 0; t < T; t++) {
        CP_WAIT(1);
        __syncthreads();
        issue(t + 2);
        int s = t - (t / ST) * ST;
        const float* sA = As + s * TW;
        const float* sB = Bs + s * TW;
        #pragma unroll
        for (int ks = 0; ks < 16; ks += 8) {
            const int q0 = ks >> 2;
            unsigned af[2][4];
            #pragma unroll
            for (int mi = 0; mi < 2; mi++) {
                const float* rp = sA + (wm0 + mi * 16 + grp) * 16;
                af[mi][0] = __float_as_uint(rp[colA[q0]]);
                af[mi][1] = __float_as_uint(rp[128 + colA[q0]]);
                af[mi][2] = __float_as_uint(rp[colA[q0 + 1]]);
                af[mi][3] = __float_as_uint(rp[128 + colA[q0 + 1]]);
            }
            unsigned bf[8][2];
            #pragma unroll
            for (int ni = 0; ni < 8; ni++) {
                const float* rp = sB + (wn0 + ni * 8 + grp) * 16;
                bf[ni][0] = __float_as_uint(rp[colB[q0]]);
                bf[ni][1] = __float_as_uint(rp[colB[q0 + 1]]);
            }
            #pragma unroll
            for (int mi = 0; mi < 2; mi++)
                #pragma unroll
                for (int ni = 0; ni < 8; ni++)
                    mma8(c[mi][ni], af[mi], bf[ni]);
        }
    }

    // ---- epilogue ----
    #pragma unroll
    for (int mi = 0; mi < 2; mi++) {
        int r0 = m0 + wm0 + mi * 16 + grp;
        #pragma unroll
        for (int ni = 0; ni < 8; ni++) {
            int col = n0 + wn0 + ni * 8 + 2 * tig;
            if (col >= N) continue;
            float bx = 0.f, by = 0.f;
            if (bias) { bx = bias[col]; by = bias[col + 1]; }
            float v0 = c[mi][ni][0] + bx, v1 = c[mi][ni][1] + by;
            float v2 = c[mi][ni][2] + bx, v3 = c[mi][ni][3] + by;
            if (EPI == 1) {
                v0 = 0.5f * v0 * (1.f + erff(v0 * 0.70710678118654752f));
                v1 = 0.5f * v1 * (1.f + erff(v1 * 0.70710678118654752f));
                v2 = 0.5f * v2 * (1.f + erff(v2 * 0.70710678118654752f));
                v3 = 0.5f * v3 * (1.f + erff(v3 * 0.70710678118654752f));
            } else if (EPI == 2) {
                v0 = (v0 > 20.f) ? v0 : log1pf(__expf(v0));
                v1 = (v1 > 20.f) ? v1 : log1pf(__expf(v1));
                v2 = (v2 > 20.f) ? v2 : log1pf(__expf(v2));
                v3 = (v3 > 20.f) ? v3 : log1pf(__expf(v3));
            }
            if (Rp) {
                float2 ra = *(const float2*)&Rp[(long long)r0 * ldc + col];
                float2 rb = *(const float2*)&Rp[(long long)(r0 + 8) * ldc + col];
                v0 += ra.x; v1 += ra.y; v2 += rb.x; v3 += rb.y;
            }
            *(float2*)&C[(long long)r0 * ldc + col] = make_float2(v0, v1);
            *(float2*)&C[(long long)(r0 + 8) * ldc + col] = make_float2(v2, v3);
        }
    }
}

// ================= R3-style GEMM kept for TB=0 (probs @ V) =================
template <int TB, int EPI, int BN>
__global__ __launch_bounds__(256, 2)
void tgemm_kernel(const float* __restrict__ A, const float* __restrict__ Bm,
                  const float* __restrict__ bias, const float* __restrict__ resid,
                  float* __restrict__ C,
                  int M, int N, int K, int lda, int ldb, int ldc,
                  int zdiv, long long sA1, long long sA2,
                  long long sB1, long long sB2,
                  long long sC1, long long sC2) {
    constexpr int NI = BN / 16;
    constexpr int NBI = BN / 64;
    __shared__ unsigned As[16][136];
    __shared__ unsigned Bs[16][136];

    int z = blockIdx.z;
    int zq = z / zdiv, zr = z - zq * zdiv;
    A += zq * sA1 + (long long)zr * sA2;
    Bm += zq * sB1 + (long long)zr * sB2;
    C += zq * sC1 + (long long)zr * sC2;
    const float* Rp = resid ? (resid + zq * sC1 + (long long)zr * sC2) : nullptr;

    const int m0 = blockIdx.y * 128, n0 = blockIdx.x * BN;
    const int tid = threadIdx.x;
    const int lane = tid & 31, warp = tid >> 5;
    const int grp = lane >> 2, tig = lane & 3;
    const int wm0 = (warp & 3) * 32;
    const int wn0 = (warp >> 2) * (BN / 2);

    const int ar = tid >> 2;
    const int akq = (tid & 3) * 4;
    const int aqx = (akq >> 2) << 3;

    const int bkr = (BN == 128) ? (tid >> 5) : (tid >> 4);
    const int bnq = (BN == 128) ? ((tid & 31) * 4) : ((tid & 15) * 4);

    float c[2][NI][4];
    #pragma unroll
    for (int mi = 0; mi < 2; mi++)
        #pragma unroll
        for (int ni = 0; ni < NI; ni++)
            #pragma unroll
            for (int j = 0; j < 4; j++) c[mi][ni][j] = 0.f;

    float4 aR[2], bR[2];
    const float4 z4 = make_float4(0.f, 0.f, 0.f, 0.f);

    auto loadTiles = [&](int kt) {
        #pragma unroll
        for (int i = 0; i < 2; i++)
            aR[i] = *(const float4*)&A[(long long)(m0 + ar + i * 64) * lda + kt + akq];
        #pragma unroll
        for (int i = 0; i < NBI; i++) {
            if (TB) {
                int bn = n0 + ar + i * 64;
                bR[i] = (bn < N) ? *(const float4*)&Bm[(long long)bn * ldb + kt + akq] : z4;
            } else {
                int nn = n0 + bnq;
                int kk = kt + bkr + i * 8;
                bR[i] = (nn < N) ? *(const float4*)&Bm[(long long)kk * ldb + nn] : z4;
            }
        }
    };
    auto storeTiles = [&]() {
        #pragma unroll
        for (int i = 0; i < 2; i++) {
            int m = (ar + i * 64) ^ aqx;
            As[akq + 0][m] = f2tf(aR[i].x);
            As[akq + 1][m] = f2tf(aR[i].y);
            As[akq + 2][m] = f2tf(aR[i].z);
            As[akq + 3][m] = f2tf(aR[i].w);
        }
        #pragma unroll
        for (int i = 0; i < NBI; i++) {
            if (TB) {
                int n = (ar + i * 64) ^ aqx;
                Bs[akq + 0][n] = f2tf(bR[i].x);
                Bs[akq + 1][n] = f2tf(bR[i].y);
                Bs[akq + 2][n] = f2tf(bR[i].z);
                Bs[akq + 3][n] = f2tf(bR[i].w);
            } else {
                int kk = bkr + i * 8;
                int qx = ((kk >> 2) & 3) << 3;
                uint4 u;
                u.x = f2tf(bR[i].x); u.y = f2tf(bR[i].y);
                u.z = f2tf(bR[i].z); u.w = f2tf(bR[i].w);
                *(uint4*)&Bs[kk][bnq ^ qx] = u;
            }
        }
    };

    loadTiles(0);
    storeTiles();
    __syncthreads();

    for (int kt = 0; kt < K; kt += 16) {
        bool more = (kt + 16) < K;
        if (more) loadTiles(kt + 16);

        #pragma unroll
        for (int ks = 0; ks < 16; ks += 8) {
            const int xlo = (ks >> 2) << 3;
            const int xhi = xlo + 8;
            unsigned af[2][4];
            #pragma unroll
            for (int mi = 0; mi < 2; mi++) {
                int m = wm0 + mi * 16 + grp;
                af[mi][0] = As[ks + tig][m ^ xlo];
                af[mi][1] = As[ks + tig][(m + 8) ^ xlo];
                af[mi][2] = As[ks + tig + 4][m ^ xhi];
                af[mi][3] = As[ks + tig + 4][(m + 8) ^ xhi];
            }
            unsigned bf[NI][2];
            #pragma unroll
            for (int ni = 0; ni < NI; ni++) {
                int n = wn0 + ni * 8 + grp;
                bf[ni][0] = Bs[ks + tig][n ^ xlo];
                bf[ni][1] = Bs[ks + tig + 4][n ^ xhi];
            }
            #pragma unroll
            for (int mi = 0; mi < 2; mi++)
                #pragma unroll
                for (int ni = 0; ni < NI; ni++)
                    mma8(c[mi][ni], af[mi], bf[ni]);
        }
        __syncthreads();
        if (more) {
            storeTiles();
            __syncthreads();
        }
    }

    #pragma unroll
    for (int mi = 0; mi < 2; mi++) {
        int r0 = m0 + wm0 + mi * 16 + grp;
        #pragma unroll
        for (int ni = 0; ni < NI; ni++) {
            int col = n0 + wn0 + ni * 8 + 2 * tig;
            if (col >= N) continue;
            float bx = 0.f, by = 0.f;
            if (bias) { bx = bias[col]; by = bias[col + 1]; }
            float v0 = c[mi][ni][0] + bx, v1 = c[mi][ni][1] + by;
            float v2 = c[mi][ni][2] + bx, v3 = c[mi][ni][3] + by;
            if (Rp) {
                float2 ra = *(const float2*)&Rp[(long long)r0 * ldc + col];
                float2 rb = *(const float2*)&Rp[(long long)(r0 + 8) * ldc + col];
                v0 += ra.x; v1 += ra.y; v2 += rb.x; v3 += rb.y;
            }
            *(float2*)&C[(long long)r0 * ldc + col] = make_float2(v0, v1);
            *(float2*)&C[(long long)(r0 + 8) * ldc + col] = make_float2(v2, v3);
        }
    }
}

// ---------------- softmax: single pass over gmem via smem row cache ----------------
__global__ void softmax_kernel(float* __restrict__ sc, const unsigned char* __restrict__ mask) {
    __shared__ float row[CL];
    long long r = blockIdx.x;                 // b*H*L + h*L + l
    int b = (int)(r / ((long long)CH * CL));
    float* p = sc + r * (long long)CL;
    const unsigned char* mrow = mask + (long long)b * CL;
    const float scale = 0.125f;               // 1/sqrt(64)

    float mx = -INFINITY;
    for (int s = threadIdx.x; s < CL; s += blockDim.x) {
        float v = mrow[s] ? -INFINITY : p[s] * scale;
        row[s] = v;
        mx = fmaxf(mx, v);
    }
    mx = blockMax(mx);
    float sum = 0.f;
    for (int s = threadIdx.x; s < CL; s += blockDim.x) {
        float e = __expf(row[s] - mx);
        row[s] = e;
        sum += e;
    }
    sum = blockSum(sum);
    float inv = 1.f / sum;
    for (int s = threadIdx.x; s < CL; s += blockDim.x) p[s] = row[s] * inv;
}

// ---------------- causal depthwise conv (KC=4) + SiLU ----------------
__global__ void conv_silu_kernel(const float* __restrict__ xz, const float* __restrict__ cw,
                                 const float* __restrict__ cb, float* __restrict__ uact) {
    long long idx = (long long)blockIdx.x * blockDim.x + threadIdx.x;
    if (idx >= (long long)CM * CDI) return;
    int di = (int)(idx % CDI);
    long long bl = idx / CDI;          // b*L + t
    int t = (int)(bl % CL);
    long long bbase = bl - t;          // b*L
    float acc = cb[di];
    #pragma unroll
    for (int kk = 0; kk < CKC; kk++) {
        int t2 = t + kk - (CKC - 1);
        if (t2 >= 0)
            acc = fmaf(xz[(bbase + t2) * (long long)(2 * CDI) + di], cw[di * CKC + kk], acc);
    }
    float sg = 1.f / (1.f + __expf(-acc));
    uact[idx] = acc * sg;
}

// ---------------- selective scan: one warp per (b,di) chain, 2 states/lane ----------------
__global__ void scan_kernel(const float* __restrict__ delta, const float* __restrict__ uact,
                            const float* __restrict__ xdbc, const float* __restrict__ xz,
                            const float* __restrict__ A_log, const float* __restrict__ D_ssm,
                            float* __restrict__ y) {
    int wg = (int)(((long long)blockIdx.x * blockDim.x + threadIdx.x) >> 5);
    int lane = threadIdx.x & 31;
    if (wg >= CB * CDI) return;
    int b = wg >> 10;            // / CDI
    int di = wg & (CDI - 1);

    float a0 = -__expf(A_log[di * CS + lane]);
    float a1 = -__expf(A_log[di * CS + lane + 32]);
    float Dd = D_ssm[di];
    float h0 = 0.f, h1 = 0.f;

    const float* dptr = delta + (long long)b * CL * CDI + di;
    const float* uptr = uact + (long long)b * CL * CDI + di;
    const float* zptr = xz + (long long)b * CL * (2 * CDI) + CDI + di;
    const float* bc = xdbc + (long long)b * CL * (CR + 2 * CS);
    float* yptr = y + (long long)b * CL * CDI + di;

    for (int t = 0; t < CL; t++) {
        float dt = dptr[(long long)t * CDI];
        float uu = uptr[(long long)t * CDI];
        const float* xrow = bc + (long long)t * (CR + 2 * CS);
        float B0 = xrow[CR + lane];
        float B1 = xrow[CR + 32 + lane];
        float C0 = xrow[CR + CS + lane];
        float C1 = xrow[CR + CS + 32 + lane];
        float dA0 = __expf(dt * a0);
        float dA1 = __expf(dt * a1);
        float du = dt * uu;
        h0 = fmaf(h0, dA0, du * B0);
        h1 = fmaf(h1, dA1, du * B1);
        float acc = fmaf(h0, C0, h1 * C1);
        #pragma unroll
        for (int o = 16; o; o >>= 1) acc += __shfl_down_sync(0xffffffffu, acc, o);
        if (lane == 0) {
            float zv = zptr[(long long)t * (2 * CDI)];
            float sz = zv / (1.f + __expf(-zv));
            yptr[(long long)t * CDI] = (acc + uu * Dd) * sz;
        }
    }
}

// ---------------- residual add3 + LN1 + LN2 (both in one kernel) ----------------
__global__ void add_ln_kernel(const float* __restrict__ x, const float* __restrict__ attn,
                              const float* __restrict__ mamba,
                              const float* __restrict__ g1, const float* __restrict__ b1,
                              const float* __restrict__ g2, const float* __restrict__ b2,
                              float* __restrict__ hout, float* __restrict__ hnout) {
    long long row = blockIdx.x;
    const long long base = row * CD;
    float s[4];
    #pragma unroll
    for (int i = 0; i < 4; i++) {
        int c = threadIdx.x + i * 128;
        s[i] = x[base + c] + attn[base + c] + mamba[base + c];
    }
    float sum = s[0] + s[1] + s[2] + s[3];
    float mean = blockSum(sum) * (1.f / CD);
    float vs = 0.f;
    #pragma unroll
    for (int i = 0; i < 4; i++) { float d = s[i] - mean; vs += d * d; }
    float var = blockSum(vs) * (1.f / CD);
    float inv = rsqrtf(var + 1e-5f);
    float h[4];
    #pragma unroll
    for (int i = 0; i < 4; i++) {
        int c = threadIdx.x + i * 128;
        h[i] = (s[i] - mean) * inv * g1[c] + b1[c];
        hout[base + c] = h[i];
    }
    float sum2 = h[0] + h[1] + h[2] + h[3];
    float mean2 = blockSum(sum2) * (1.f / CD);
    float vs2 = 0.f;
    #pragma unroll
    for (int i = 0; i < 4; i++) { float d = h[i] - mean2; vs2 += d * d; }
    float var2 = blockSum(vs2) * (1.f / CD);
    float inv2 = rsqrtf(var2 + 1e-6f);
    #pragma unroll
    for (int i = 0; i < 4; i++) {
        int c = threadIdx.x + i * 128;
        hnout[base + c] = (h[i] - mean2) * inv2 * g2[c] + b2[c];
    }
}

// ---------------- host ----------------
static inline dim3 tg_grid(int M, int N, int BN, int batch) {
    return dim3((N + BN - 1) / BN, (M + 127) / 128, batch);
}

extern "C" void kernel_launch(void* const* d_in, const int* in_sizes, int n_in,
                              void* d_out, int out_size) {
    const float* x          = (const float*)d_in[0];
    const unsigned char* mask = (const unsigned char*)d_in[1];
    const float* Wq = (const float*)d_in[2];
    const float* bq = (const float*)d_in[3];
    const float* Wk = (const float*)d_in[4];
    const float* bk = (const float*)d_in[5];
    const float* Wv = (const float*)d_in[6];
    const float* bv = (const float*)d_in[7];
    const float* Wo = (const float*)d_in[8];
    const float* bo = (const float*)d_in[9];
    const float* in_proj_w = (const float*)d_in[10];
    const float* conv_w    = (const float*)d_in[11];
    const float* conv_b    = (const float*)d_in[12];
    const float* x_proj_w  = (const float*)d_in[13];
    const float* dt_proj_w = (const float*)d_in[14];
    const float* dt_proj_b = (const float*)d_in[15];
    const float* A_log     = (const float*)d_in[16];
    const float* D_ssm     = (const float*)d_in[17];
    const float* out_proj_w = (const float*)d_in[18];
    const float* ln1_g = (const float*)d_in[19];
    const float* ln1_b = (const float*)d_in[20];
    const float* ffn_w1 = (const float*)d_in[21];
    const float* ffn_b1 = (const float*)d_in[22];
    const float* ffn_w2 = (const float*)d_in[23];
    const float* ffn_b2 = (const float*)d_in[24];
    const float* ln2_g = (const float*)d_in[25];
    const float* ln2_b = (const float*)d_in[26];
    float* out = (float*)d_out;

    float *q, *k, *v, *scores, *attn, *xattn, *xz, *uact, *xdbc, *delta, *yss, *mamba, *h, *hn, *ff1;
    cudaGetSymbolAddress((void**)&q, g_q);
    cudaGetSymbolAddress((void**)&k, g_k);
    cudaGetSymbolAddress((void**)&v, g_v);
    cudaGetSymbolAddress((void**)&scores, g_scores);
    cudaGetSymbolAddress((void**)&attn, g_attn);
    cudaGetSymbolAddress((void**)&xattn, g_xattn);
    cudaGetSymbolAddress((void**)&xz, g_xz);
    cudaGetSymbolAddress((void**)&uact, g_uact);
    cudaGetSymbolAddress((void**)&xdbc, g_xdbc);
    cudaGetSymbolAddress((void**)&delta, g_delta);
    cudaGetSymbolAddress((void**)&yss, g_yss);
    cudaGetSymbolAddress((void**)&mamba, g_mamba);
    cudaGetSymbolAddress((void**)&h, g_h);
    cudaGetSymbolAddress((void**)&hn, g_hn);
    cudaGetSymbolAddress((void**)&ff1, g_ff1);

    // ---- attention ----
    tgemm2_kernel<0><<<tg_grid(CM, CD, 128, 1), 256>>>(
        x, Wq, bq, nullptr, q, CM, CD, CD, CD, CD, CD, 1, 0, 0, 0, 0, 0, 0);
    tgemm2_kernel<0><<<tg_grid(CM, CD, 128, 1), 256>>>(
        x, Wk, bk, nullptr, k, CM, CD, CD, CD, CD, CD, 1, 0, 0, 0, 0, 0, 0);
    tgemm2_kernel<0><<<tg_grid(CM, CD, 128, 1), 256>>>(
        x, Wv, bv, nullptr, v, CM, CD, CD, CD, CD, CD, 1, 0, 0, 0, 0, 0, 0);

    // scores[b,h,l,s] = q[b,l,h,:] . k[b,s,h,:]   (batched over z = b*H+h)
    tgemm2_kernel<0><<<tg_grid(CL, CL, 128, CB * CH), 256>>>(
        q, k, nullptr, nullptr, scores, CL, CL, CE, CD, CD, CL,
        CH,
        (long long)CL * CD, CE,
        (long long)CL * CD, CE,
        (long long)CH * CL * CL, (long long)CL * CL);

    softmax_kernel<<<CB * CH * CL, 256>>>(scores, mask);

    // attn[b,l,h,:] = sum_s probs[b,h,l,s] * v[b,s,h,:]   (NN batched, BN=64)
    tgemm_kernel<0, 0, 64><<<tg_grid(CL, CE, 64, CB * CH), 256>>>(
        scores, v, nullptr, nullptr, attn, CL, CE, CL, CL, CD, CD,
        CH,
        (long long)CH * CL * CL, (long long)CL * CL,
        (long long)CL * CD, CE,
        (long long)CL * CD, CE);

    tgemm2_kernel<0><<<tg_grid(CM, CD, 128, 1), 256>>>(
        attn, Wo, bo, nullptr, xattn, CM, CD, CD, CD, CD, CD, 1, 0, 0, 0, 0, 0, 0);

    // ---- mamba ----
    tgemm2_kernel<0><<<tg_grid(CM, 2 * CDI, 128, 1), 256>>>(
        x, in_proj_w, nullptr, nullptr, xz, CM, 2 * CDI, CD, CD, CD, 2 * CDI,
        1, 0, 0, 0, 0, 0, 0);

    {
        long long n = (long long)CM * CDI;
        conv_silu_kernel<<<(unsigned)((n + 255) / 256), 256>>>(xz, conv_w, conv_b, uact);
    }

    tgemm2_kernel<0><<<tg_grid(CM, CR + 2 * CS, 128, 1), 256>>>(
        uact, x_proj_w, nullptr, nullptr, xdbc, CM, CR + 2 * CS, CDI,
        CDI, CDI, CR + 2 * CS, 1, 0, 0, 0, 0, 0, 0);

    tgemm2_kernel<2><<<tg_grid(CM, CDI, 128, 1), 256>>>(
        xdbc, dt_proj_w, dt_proj_b, nullptr, delta, CM, CDI, CR,
        CR + 2 * CS, CR, CDI, 1, 0, 0, 0, 0, 0, 0);

    scan_kernel<<<(CB * CDI * 32) / 256, 256>>>(delta, uact, xdbc, xz, A_log, D_ssm, yss);

    tgemm2_kernel<0><<<tg_grid(CM, CD, 128, 1), 256>>>(
        yss, out_proj_w, nullptr, nullptr, mamba, CM, CD, CDI, CDI, CDI, CD,
        1, 0, 0, 0, 0, 0, 0);

    // ---- residual + LN1 + LN2 ----
    add_ln_kernel<<<CM, 128>>>(x, xattn, mamba, ln1_g, ln1_b, ln2_g, ln2_b, h, hn);

    // ---- FFN (GELU epilogue; residual fused into second GEMM) ----
    tgemm2_kernel<1><<<tg_grid(CM, CDFF, 128, 1), 256>>>(
        hn, ffn_w1, ffn_b1, nullptr, ff1, CM, CDFF, CD, CD, CD, CDFF,
        1, 0, 0, 0, 0, 0, 0);
    tgemm2_kernel<0><<<tg_grid(CM, CD, 128, 1), 256>>>(
        ff1, ffn_w2, ffn_b2, h, out, CM, CD, CDFF, CDFF, CDFF, CD,
        1, 0, 0, 0, 0, 0, 0);
}

// round 10
// speedup vs baseline: 1.3317x; 1.3317x over previous
#include <cuda_runtime.h>
#include <math.h>

// ---------------- problem constants ----------------
#define CB   8
#define CD   512
#define CH   8
#define CE   64
#define CDI  1024
#define CS   64
#define CR   32
#define CKC  4
#define CDFF 2048
#define CL   1152          // T*W
#define CM   9216          // B*L

// ---------------- scratch ----------------
__device__ float g_q[CM * CD];
__device__ float g_k[CM * CD];
__device__ float g_v[CM * CD];
__device__ float g_attn[CM * CD];
__device__ float g_xattn[CM * CD];
__device__ float g_xz[CM * 2 * CDI];
__device__ float g_uact[CM * CDI];
__device__ float g_xdbc[CM * (CR + 2 * CS)];
__device__ float g_delta[CM * CDI];
__device__ float g_yss[CM * CDI];
__device__ float g_mamba[CM * CD];
__device__ float g_h[CM * CD];
__device__ float g_hn[CM * CD];
__device__ float g_ff1[CM * CDFF];

// ---------------- reductions ----------------
__device__ __forceinline__ float warpSum(float v) {
    #pragma unroll
    for (int o = 16; o; o >>= 1) v += __shfl_xor_sync(0xffffffffu, v, o);
    return v;
}
__device__ float blockSum(float v) {
    __shared__ float sh[32];
    int lane = threadIdx.x & 31, wid = threadIdx.x >> 5;
    v = warpSum(v);
    if (lane == 0) sh[wid] = v;
    __syncthreads();
    int nw = blockDim.x >> 5;
    v = (threadIdx.x < nw) ? sh[threadIdx.x] : 0.f;
    if (wid == 0) v = warpSum(v);
    if (threadIdx.x == 0) sh[0] = v;
    __syncthreads();
    float r = sh[0];
    __syncthreads();
    return r;
}

// ---------------- tf32 helpers ----------------
__device__ __forceinline__ unsigned f2tf(float f) {
    unsigned u;
    asm("cvt.rna.tf32.f32 %0, %1;" : "=r"(u) : "f"(f));
    return u;
}
__device__ __forceinline__ void mma8(float* c, const unsigned* a, const unsigned* b) {
    asm volatile("mma.sync.aligned.m16n8k8.row.col.f32.tf32.tf32.f32 "
                 "{%0,%1,%2,%3}, {%4,%5,%6,%7}, {%8,%9}, {%0,%1,%2,%3};\n"
                 : "+f"(c[0]), "+f"(c[1]), "+f"(c[2]), "+f"(c[3])
                 : "r"(a[0]), "r"(a[1]), "r"(a[2]), "r"(a[3]),
                   "r"(b[0]), "r"(b[1]));
}

// ================= R3 proven tf32 GEMM =================
// TB=1: C[m,n] = sum_k A[m,k]*B[n,k]; TB=0: C = A*B (NN)
template <int TB, int EPI, int BN>
__global__ __launch_bounds__(256, 2)
void tgemm_kernel(const float* __restrict__ A, const float* __restrict__ Bm,
                  const float* __restrict__ bias, const float* __restrict__ resid,
                  float* __restrict__ C,
                  int M, int N, int K, int lda, int ldb, int ldc,
                  int zdiv, long long sA1, long long sA2,
                  long long sB1, long long sB2,
                  long long sC1, long long sC2) {
    constexpr int NI = BN / 16;
    constexpr int NBI = BN / 64;
    __shared__ unsigned As[16][136];
    __shared__ unsigned Bs[16][136];

    int z = blockIdx.z;
    int zq = z / zdiv, zr = z - zq * zdiv;
    A += zq * sA1 + (long long)zr * sA2;
    Bm += zq * sB1 + (long long)zr * sB2;
    C += zq * sC1 + (long long)zr * sC2;
    const float* Rp = resid ? (resid + zq * sC1 + (long long)zr * sC2) : nullptr;

    const int m0 = blockIdx.y * 128, n0 = blockIdx.x * BN;
    const int tid = threadIdx.x;
    const int lane = tid & 31, warp = tid >> 5;
    const int grp = lane >> 2, tig = lane & 3;
    const int wm0 = (warp & 3) * 32;
    const int wn0 = (warp >> 2) * (BN / 2);

    const int ar = tid >> 2;
    const int akq = (tid & 3) * 4;
    const int aqx = (akq >> 2) << 3;

    const int bkr = (BN == 128) ? (tid >> 5) : (tid >> 4);
    const int bnq = (BN == 128) ? ((tid & 31) * 4) : ((tid & 15) * 4);

    float c[2][NI][4];
    #pragma unroll
    for (int mi = 0; mi < 2; mi++)
        #pragma unroll
        for (int ni = 0; ni < NI; ni++)
            #pragma unroll
            for (int j = 0; j < 4; j++) c[mi][ni][j] = 0.f;

    float4 aR[2], bR[2];
    const float4 z4 = make_float4(0.f, 0.f, 0.f, 0.f);

    auto loadTiles = [&](int kt) {
        #pragma unroll
        for (int i = 0; i < 2; i++)
            aR[i] = *(const float4*)&A[(long long)(m0 + ar + i * 64) * lda + kt + akq];
        #pragma unroll
        for (int i = 0; i < NBI; i++) {
            if (TB) {
                int bn = n0 + ar + i * 64;
                bR[i] = (bn < N) ? *(const float4*)&Bm[(long long)bn * ldb + kt + akq] : z4;
            } else {
                int nn = n0 + bnq;
                int kk = kt + bkr + i * 8;
                bR[i] = (nn < N) ? *(const float4*)&Bm[(long long)kk * ldb + nn] : z4;
            }
        }
    };
    auto storeTiles = [&]() {
        #pragma unroll
        for (int i = 0; i < 2; i++) {
            int m = (ar + i * 64) ^ aqx;
            As[akq + 0][m] = f2tf(aR[i].x);
            As[akq + 1][m] = f2tf(aR[i].y);
            As[akq + 2][m] = f2tf(aR[i].z);
            As[akq + 3][m] = f2tf(aR[i].w);
        }
        #pragma unroll
        for (int i = 0; i < NBI; i++) {
            if (TB) {
                int n = (ar + i * 64) ^ aqx;
                Bs[akq + 0][n] = f2tf(bR[i].x);
                Bs[akq + 1][n] = f2tf(bR[i].y);
                Bs[akq + 2][n] = f2tf(bR[i].z);
                Bs[akq + 3][n] = f2tf(bR[i].w);
            } else {
                int kk = bkr + i * 8;
                int qx = ((kk >> 2) & 3) << 3;
                uint4 u;
                u.x = f2tf(bR[i].x); u.y = f2tf(bR[i].y);
                u.z = f2tf(bR[i].z); u.w = f2tf(bR[i].w);
                *(uint4*)&Bs[kk][bnq ^ qx] = u;
            }
        }
    };

    loadTiles(0);
    storeTiles();
    __syncthreads();

    for (int kt = 0; kt < K; kt += 16) {
        bool more = (kt + 16) < K;
        if (more) loadTiles(kt + 16);

        #pragma unroll
        for (int ks = 0; ks < 16; ks += 8) {
            const int xlo = (ks >> 2) << 3;
            const int xhi = xlo + 8;
            unsigned af[2][4];
            #pragma unroll
            for (int mi = 0; mi < 2; mi++) {
                int m = wm0 + mi * 16 + grp;
                af[mi][0] = As[ks + tig][m ^ xlo];
                af[mi][1] = As[ks + tig][(m + 8) ^ xlo];
                af[mi][2] = As[ks + tig + 4][m ^ xhi];
                af[mi][3] = As[ks + tig + 4][(m + 8) ^ xhi];
            }
            unsigned bf[NI][2];
            #pragma unroll
            for (int ni = 0; ni < NI; ni++) {
                int n = wn0 + ni * 8 + grp;
                bf[ni][0] = Bs[ks + tig][n ^ xlo];
                bf[ni][1] = Bs[ks + tig + 4][n ^ xhi];
            }
            #pragma unroll
            for (int mi = 0; mi < 2; mi++)
                #pragma unroll
                for (int ni = 0; ni < NI; ni++)
                    mma8(c[mi][ni], af[mi], bf[ni]);
        }
        __syncthreads();
        if (more) {
            storeTiles();
            __syncthreads();
        }
    }

    #pragma unroll
    for (int mi = 0; mi < 2; mi++) {
        int r0 = m0 + wm0 + mi * 16 + grp;
        #pragma unroll
        for (int ni = 0; ni < NI; ni++) {
            int col = n0 + wn0 + ni * 8 + 2 * tig;
            if (col >= N) continue;
            float bx = 0.f, by = 0.f;
            if (bias) { bx = bias[col]; by = bias[col + 1]; }
            float v0 = c[mi][ni][0] + bx, v1 = c[mi][ni][1] + by;
            float v2 = c[mi][ni][2] + bx, v3 = c[mi][ni][3] + by;
            if (EPI == 1) {
                v0 = 0.5f * v0 * (1.f + erff(v0 * 0.70710678118654752f));
                v1 = 0.5f * v1 * (1.f + erff(v1 * 0.70710678118654752f));
                v2 = 0.5f * v2 * (1.f + erff(v2 * 0.70710678118654752f));
                v3 = 0.5f * v3 * (1.f + erff(v3 * 0.70710678118654752f));
            } else if (EPI == 2) {
                v0 = (v0 > 20.f) ? v0 : log1pf(__expf(v0));
                v1 = (v1 > 20.f) ? v1 : log1pf(__expf(v1));
                v2 = (v2 > 20.f) ? v2 : log1pf(__expf(v2));
                v3 = (v3 > 20.f) ? v3 : log1pf(__expf(v3));
            }
            if (Rp) {
                float2 ra = *(const float2*)&Rp[(long long)r0 * ldc + col];
                float2 rb = *(const float2*)&Rp[(long long)(r0 + 8) * ldc + col];
                v0 += ra.x; v1 += ra.y; v2 += rb.x; v3 += rb.y;
            }
            *(float2*)&C[(long long)r0 * ldc + col] = make_float2(v0, v1);
            *(float2*)&C[(long long)(r0 + 8) * ldc + col] = make_float2(v2, v3);
        }
    }
}

// ================= flash attention =================
// grid (9, 64): x = q-tile (128 rows), y = b*8+h. 256 threads.
// Q pre-scaled by 1/8, staged once; K/V tiles per s-iter; online softmax; O accum in regs.
#define QS_N  (64 * 136)
#define VT_ST 133
#define PS_ST 134
__global__ __launch_bounds__(256, 1)
void flash_kernel(const float* __restrict__ qg, const float* __restrict__ kg,
                  const float* __restrict__ vg, const unsigned char* __restrict__ maskg,
                  float* __restrict__ og) {
    extern __shared__ float smf[];
    unsigned* Qs = (unsigned*)smf;                   // [64][136]
    unsigned* Ks = (unsigned*)(smf + QS_N);          // [64][136]
    float* Vt = smf + 2 * QS_N;                      // [64][133]
    float* Ps = smf + 2 * QS_N + 64 * VT_ST;         // [128][134]
    float* sm_m  = Ps + 128 * PS_ST;                 // 128
    float* sm_l  = sm_m + 128;                       // 128
    float* sm_al = sm_l + 128;                       // 128
    float* pmax  = sm_al + 128;                      // [2][128]
    float* psum  = pmax + 256;                       // [2][128]
    unsigned char* msk = (unsigned char*)(psum + 256);  // 128 bytes

    const int tid = threadIdx.x;
    const int lane = tid & 31, warp = tid >> 5;
    const int grp = lane >> 2, tig = lane & 3;
    const int wm0 = (warp & 3) * 32;                 // S layout
    const int wn0 = (warp >> 2) * 64;
    const int wc  = warp >> 2;
    const int wmP = warp * 16;                       // PV layout

    const int q0 = blockIdx.x * 128;
    const int b = blockIdx.y >> 3, h = blockIdx.y & 7;
    const long long bL = (long long)b * CL;
    const float* qbase = qg + (bL + q0) * CD + h * 64;
    const float* kbase = kg + bL * CD + h * 64;
    const float* vbase = vg + bL * CD + h * 64;
    const unsigned char* mbase = maskg + bL;

    if (tid < 128) { sm_m[tid] = -INFINITY; sm_l[tid] = 0.f; }

    // ---- stage Q (scaled, tf32) into Qs[k][m^swz] ----
    const int r_ld = tid >> 2;
    const int akq = (tid & 3) * 4;
    const int aqx = ((akq >> 2) & 3) << 3;
    #pragma unroll
    for (int kt2 = 0; kt2 < 4; kt2++) {
        #pragma unroll
        for (int i = 0; i < 2; i++) {
            int m = r_ld + i * 64;
            float4 v4 = *(const float4*)&qbase[(long long)m * CD + kt2 * 16 + akq];
            int col = m ^ aqx;
            int kb = kt2 * 16 + akq;
            Qs[(kb + 0) * 136 + col] = f2tf(v4.x * 0.125f);
            Qs[(kb + 1) * 136 + col] = f2tf(v4.y * 0.125f);
            Qs[(kb + 2) * 136 + col] = f2tf(v4.z * 0.125f);
            Qs[(kb + 3) * 136 + col] = f2tf(v4.w * 0.125f);
        }
    }

    float o[8][4];
    #pragma unroll
    for (int ni = 0; ni < 8; ni++)
        #pragma unroll
        for (int j = 0; j < 4; j++) o[ni][j] = 0.f;

    const int ve = tid & 63, vsb = (tid >> 6) * 32;

    for (int it = 0; it < 9; it++) {
        const int s0 = it * 128;
        __syncthreads();   // protect Ks/Vt/msk (prev PV done)

        // ---- load K tile -> Ks[k][n^swz] ----
        #pragma unroll
        for (int kt2 = 0; kt2 < 4; kt2++) {
            #pragma unroll
            for (int i = 0; i < 2; i++) {
                int n = r_ld + i * 64;
                float4 v4 = *(const float4*)&kbase[(long long)(s0 + n) * CD + kt2 * 16 + akq];
                int col = n ^ aqx;
                int kb = kt2 * 16 + akq;
                Ks[(kb + 0) * 136 + col] = f2tf(v4.x);
                Ks[(kb + 1) * 136 + col] = f2tf(v4.y);
                Ks[(kb + 2) * 136 + col] = f2tf(v4.z);
                Ks[(kb + 3) * 136 + col] = f2tf(v4.w);
            }
        }
        // ---- load V tile transposed -> Vt[e][s] ----
        #pragma unroll 4
        for (int i = 0; i < 32; i++) {
            int s = vsb + i;
            float v = vbase[(long long)(s0 + s) * CD + ve];
            Vt[ve * VT_ST + s] = __uint_as_float(f2tf(v));
        }
        if (tid < 128) msk[tid] = mbase[s0 + tid];
        __syncthreads();

        // ---- S = Q K^T (128x128, K=64) ----
        float c[2][8][4];
        #pragma unroll
        for (int mi = 0; mi < 2; mi++)
            #pragma unroll
            for (int ni = 0; ni < 8; ni++)
                #pragma unroll
                for (int j = 0; j < 4; j++) c[mi][ni][j] = 0.f;
        #pragma unroll
        for (int ks = 0; ks < 64; ks += 8) {
            const int xlo = ((ks >> 2) & 3) << 3;
            const int xhi = (((ks + 4) >> 2) & 3) << 3;
            unsigned af[2][4];
            #pragma unroll
            for (int mi = 0; mi < 2; mi++) {
                int m = wm0 + mi * 16 + grp;
                af[mi][0] = Qs[(ks + tig) * 136 + (m ^ xlo)];
                af[mi][1] = Qs[(ks + tig) * 136 + ((m + 8) ^ xlo)];
                af[mi][2] = Qs[(ks + tig + 4) * 136 + (m ^ xhi)];
                af[mi][3] = Qs[(ks + tig + 4) * 136 + ((m + 8) ^ xhi)];
            }
            unsigned bf[8][2];
            #pragma unroll
            for (int ni = 0; ni < 8; ni++) {
                int n = wn0 + ni * 8 + grp;
                bf[ni][0] = Ks[(ks + tig) * 136 + (n ^ xlo)];
                bf[ni][1] = Ks[(ks + tig + 4) * 136 + (n ^ xhi)];
            }
            #pragma unroll
            for (int mi = 0; mi < 2; mi++)
                #pragma unroll
                for (int ni = 0; ni < 8; ni++)
                    mma8(c[mi][ni], af[mi], bf[ni]);
        }

        // ---- per-row tile max (mask applied) ----
        #pragma unroll
        for (int mi = 0; mi < 2; mi++) {
            #pragma unroll
            for (int p = 0; p < 2; p++) {
                float tm = -INFINITY;
                #pragma unroll
                for (int ni = 0; ni < 8; ni++) {
                    int col = wn0 + ni * 8 + 2 * tig;
                    float a = msk[col] ? -INFINITY : c[mi][ni][2 * p];
                    float bb = msk[col + 1] ? -INFINITY : c[mi][ni][2 * p + 1];
                    tm = fmaxf(tm, fmaxf(a, bb));
                }
                tm = fmaxf(tm, __shfl_xor_sync(0xffffffffu, tm, 1));
                tm = fmaxf(tm, __shfl_xor_sync(0xffffffffu, tm, 2));
                if (tig == 0) pmax[wc * 128 + wm0 + mi * 16 + grp + 8 * p] = tm;
            }
        }
        __syncthreads();

        if (tid < 128) {
            float mo = sm_m[tid];
            float nm = fmaxf(mo, fmaxf(pmax[tid], pmax[128 + tid]));
            float al = (nm == -INFINITY) ? 1.f : __expf(mo - nm);
            sm_al[tid] = al;
            sm_m[tid] = nm;
        }
        __syncthreads();

        // ---- exp, store P, row sums ----
        #pragma unroll
        for (int mi = 0; mi < 2; mi++) {
            #pragma unroll
            for (int p = 0; p < 2; p++) {
                int row = wm0 + mi * 16 + grp + 8 * p;
                float nm = sm_m[row];
                float rs = 0.f;
                #pragma unroll
                for (int ni = 0; ni < 8; ni++) {
                    int col = wn0 + ni * 8 + 2 * tig;
                    float e0 = msk[col]     ? 0.f : __expf(c[mi][ni][2 * p] - nm);
                    float e1 = msk[col + 1] ? 0.f : __expf(c[mi][ni][2 * p + 1] - nm);
                    rs += e0 + e1;
                    *(float2*)&Ps[row * PS_ST + col] = make_float2(e0, e1);
                }
                rs += __shfl_xor_sync(0xffffffffu, rs, 1);
                rs += __shfl_xor_sync(0xffffffffu, rs, 2);
                if (tig == 0) psum[wc * 128 + row] = rs;
            }
        }
        __syncthreads();

        // ---- rescale O, PV mma, update l ----
        {
            float al0 = sm_al[wmP + grp];
            float al1 = sm_al[wmP + grp + 8];
            #pragma unroll
            for (int ni = 0; ni < 8; ni++) {
                o[ni][0] *= al0; o[ni][1] *= al0;
                o[ni][2] *= al1; o[ni][3] *= al1;
            }
        }
        if (tid < 128)
            sm_l[tid] = sm_l[tid] * sm_al[tid] + psum[tid] + psum[128 + tid];

        #pragma unroll
        for (int ks = 0; ks < 128; ks += 8) {
            unsigned ap[4];
            const float* pr0 = Ps + (wmP + grp) * PS_ST;
            const float* pr1 = Ps + (wmP + grp + 8) * PS_ST;
            ap[0] = __float_as_uint(pr0[ks + tig]);
            ap[1] = __float_as_uint(pr1[ks + tig]);
            ap[2] = __float_as_uint(pr0[ks + tig + 4]);
            ap[3] = __float_as_uint(pr1[ks + tig + 4]);
            #pragma unroll
            for (int ni = 0; ni < 8; ni++) {
                unsigned bv[2];
                const float* vr = Vt + (ni * 8 + grp) * VT_ST;
                bv[0] = __float_as_uint(vr[ks + tig]);
                bv[1] = __float_as_uint(vr[ks + tig + 4]);
                mma8(o[ni], ap, bv);
            }
        }
    }
    __syncthreads();

    // ---- normalize + write ----
    {
        int r0 = wmP + grp, r1 = r0 + 8;
        float il0 = 1.f / sm_l[r0];
        float il1 = 1.f / sm_l[r1];
        float* o0 = og + (bL + q0 + r0) * CD + h * 64;
        float* o1 = og + (bL + q0 + r1) * CD + h * 64;
        #pragma unroll
        for (int ni = 0; ni < 8; ni++) {
            int col = ni * 8 + 2 * tig;
            *(float2*)&o0[col] = make_float2(o[ni][0] * il0, o[ni][1] * il0);
            *(float2*)&o1[col] = make_float2(o[ni][2] * il1, o[ni][3] * il1);
        }
    }
}

// ---------------- conv + SiLU ----------------
__global__ void conv_silu_kernel(const float* __restrict__ xz, const float* __restrict__ cw,
                                 const float* __restrict__ cb, float* __restrict__ uact) {
    long long idx = (long long)blockIdx.x * blockDim.x + threadIdx.x;
    if (idx >= (long long)CM * CDI) return;
    int di = (int)(idx % CDI);
    long long bl = idx / CDI;
    int t = (int)(bl % CL);
    long long bbase = bl - t;
    float acc = cb[di];
    #pragma unroll
    for (int kk = 0; kk < CKC; kk++) {
        int t2 = t + kk - (CKC - 1);
        if (t2 >= 0)
            acc = fmaf(xz[(bbase + t2) * (long long)(2 * CDI) + di], cw[di * CKC + kk], acc);
    }
    float sg = 1.f / (1.f + __expf(-acc));
    uact[idx] = acc * sg;
}

// ---------------- selective scan ----------------
__global__ void scan_kernel(const float* __restrict__ delta, const float* __restrict__ uact,
                            const float* __restrict__ xdbc, const float* __restrict__ xz,
                            const float* __restrict__ A_log, const float* __restrict__ D_ssm,
                            float* __restrict__ y) {
    int wg = (int)(((long long)blockIdx.x * blockDim.x + threadIdx.x) >> 5);
    int lane = threadIdx.x & 31;
    if (wg >= CB * CDI) return;
    int b = wg >> 10;
    int di = wg & (CDI - 1);

    float a0 = -__expf(A_log[di * CS + lane]);
    float a1 = -__expf(A_log[di * CS + lane + 32]);
    float Dd = D_ssm[di];
    float h0 = 0.f, h1 = 0.f;

    const float* dptr = delta + (long long)b * CL * CDI + di;
    const float* uptr = uact + (long long)b * CL * CDI + di;
    const float* zptr = xz + (long long)b * CL * (2 * CDI) + CDI + di;
    const float* bc = xdbc + (long long)b * CL * (CR + 2 * CS);
    float* yptr = y + (long long)b * CL * CDI + di;

    for (int t = 0; t < CL; t++) {
        float dt = dptr[(long long)t * CDI];
        float uu = uptr[(long long)t * CDI];
        const float* xrow = bc + (long long)t * (CR + 2 * CS);
        float B0 = xrow[CR + lane];
        float B1 = xrow[CR + 32 + lane];
        float C0 = xrow[CR + CS + lane];
        float C1 = xrow[CR + CS + 32 + lane];
        float dA0 = __expf(dt * a0);
        float dA1 = __expf(dt * a1);
        float du = dt * uu;
        h0 = fmaf(h0, dA0, du * B0);
        h1 = fmaf(h1, dA1, du * B1);
        float acc = fmaf(h0, C0, h1 * C1);
        #pragma unroll
        for (int o = 16; o; o >>= 1) acc += __shfl_down_sync(0xffffffffu, acc, o);
        if (lane == 0) {
            float zv = zptr[(long long)t * (2 * CDI)];
            float sz = zv / (1.f + __expf(-zv));
            yptr[(long long)t * CDI] = (acc + uu * Dd) * sz;
        }
    }
}

// ---------------- residual add3 + LN1 + LN2 ----------------
__global__ void add_ln_kernel(const float* __restrict__ x, const float* __restrict__ attn,
                              const float* __restrict__ mamba,
                              const float* __restrict__ g1, const float* __restrict__ b1,
                              const float* __restrict__ g2, const float* __restrict__ b2,
                              float* __restrict__ hout, float* __restrict__ hnout) {
    long long row = blockIdx.x;
    const long long base = row * CD;
    float s[4];
    #pragma unroll
    for (int i = 0; i < 4; i++) {
        int c = threadIdx.x + i * 128;
        s[i] = x[base + c] + attn[base + c] + mamba[base + c];
    }
    float sum = s[0] + s[1] + s[2] + s[3];
    float mean = blockSum(sum) * (1.f / CD);
    float vs = 0.f;
    #pragma unroll
    for (int i = 0; i < 4; i++) { float d = s[i] - mean; vs += d * d; }
    float var = blockSum(vs) * (1.f / CD);
    float inv = rsqrtf(var + 1e-5f);
    float h[4];
    #pragma unroll
    for (int i = 0; i < 4; i++) {
        int c = threadIdx.x + i * 128;
        h[i] = (s[i] - mean) * inv * g1[c] + b1[c];
        hout[base + c] = h[i];
    }
    float sum2 = h[0] + h[1] + h[2] + h[3];
    float mean2 = blockSum(sum2) * (1.f / CD);
    float vs2 = 0.f;
    #pragma unroll
    for (int i = 0; i < 4; i++) { float d = h[i] - mean2; vs2 += d * d; }
    float var2 = blockSum(vs2) * (1.f / CD);
    float inv2 = rsqrtf(var2 + 1e-6f);
    #pragma unroll
    for (int i = 0; i < 4; i++) {
        int c = threadIdx.x + i * 128;
        hnout[base + c] = (h[i] - mean2) * inv2 * g2[c] + b2[c];
    }
}

// ---------------- host ----------------
static inline dim3 tg_grid(int M, int N, int BN, int batch) {
    return dim3((N + BN - 1) / BN, (M + 127) / 128, batch);
}

extern "C" void kernel_launch(void* const* d_in, const int* in_sizes, int n_in,
                              void* d_out, int out_size) {
    const float* x          = (const float*)d_in[0];
    const unsigned char* mask = (const unsigned char*)d_in[1];
    const float* Wq = (const float*)d_in[2];
    const float* bq = (const float*)d_in[3];
    const float* Wk = (const float*)d_in[4];
    const float* bk = (const float*)d_in[5];
    const float* Wv = (const float*)d_in[6];
    const float* bv = (const float*)d_in[7];
    const float* Wo = (const float*)d_in[8];
    const float* bo = (const float*)d_in[9];
    const float* in_proj_w = (const float*)d_in[10];
    const float* conv_w    = (const float*)d_in[11];
    const float* conv_b    = (const float*)d_in[12];
    const float* x_proj_w  = (const float*)d_in[13];
    const float* dt_proj_w = (const float*)d_in[14];
    const float* dt_proj_b = (const float*)d_in[15];
    const float* A_log     = (const float*)d_in[16];
    const float* D_ssm     = (const float*)d_in[17];
    const float* out_proj_w = (const float*)d_in[18];
    const float* ln1_g = (const float*)d_in[19];
    const float* ln1_b = (const float*)d_in[20];
    const float* ffn_w1 = (const float*)d_in[21];
    const float* ffn_b1 = (const float*)d_in[22];
    const float* ffn_w2 = (const float*)d_in[23];
    const float* ffn_b2 = (const float*)d_in[24];
    const float* ln2_g = (const float*)d_in[25];
    const float* ln2_b = (const float*)d_in[26];
    float* out = (float*)d_out;

    float *q, *k, *v, *attn, *xattn, *xz, *uact, *xdbc, *delta, *yss, *mamba, *h, *hn, *ff1;
    cudaGetSymbolAddress((void**)&q, g_q);
    cudaGetSymbolAddress((void**)&k, g_k);
    cudaGetSymbolAddress((void**)&v, g_v);
    cudaGetSymbolAddress((void**)&attn, g_attn);
    cudaGetSymbolAddress((void**)&xattn, g_xattn);
    cudaGetSymbolAddress((void**)&xz, g_xz);
    cudaGetSymbolAddress((void**)&uact, g_uact);
    cudaGetSymbolAddress((void**)&xdbc, g_xdbc);
    cudaGetSymbolAddress((void**)&delta, g_delta);
    cudaGetSymbolAddress((void**)&yss, g_yss);
    cudaGetSymbolAddress((void**)&mamba, g_mamba);
    cudaGetSymbolAddress((void**)&h, g_h);
    cudaGetSymbolAddress((void**)&hn, g_hn);
    cudaGetSymbolAddress((void**)&ff1, g_ff1);

    // flash smem: Qs+Ks (2*8704) + Vt (64*133) + Ps (128*134)
    //           + stats (sm_m 128 + sm_l 128 + sm_al 128 + pmax 256 + psum 256 = 896)
    //           + mask (128 bytes = 32 floats)
    const int FLASH_SMEM = (2 * QS_N + 64 * VT_ST + 128 * PS_ST + 896 + 32) * 4;
    cudaFuncSetAttribute(flash_kernel, cudaFuncAttributeMaxDynamicSharedMemorySize, FLASH_SMEM);

    // ---- attention ----
    tgemm_kernel<1, 0, 128><<<tg_grid(CM, CD, 128, 1), 256>>>(
        x, Wq, bq, nullptr, q, CM, CD, CD, CD, CD, CD, 1, 0, 0, 0, 0, 0, 0);
    tgemm_kernel<1, 0, 128><<<tg_grid(CM, CD, 128, 1), 256>>>(
        x, Wk, bk, nullptr, k, CM, CD, CD, CD, CD, CD, 1, 0, 0, 0, 0, 0, 0);
    tgemm_kernel<1, 0, 128><<<tg_grid(CM, CD, 128, 1), 256>>>(
        x, Wv, bv, nullptr, v, CM, CD, CD, CD, CD, CD, 1, 0, 0, 0, 0, 0, 0);

    flash_kernel<<<dim3(CL / 128, CB * CH), 256, FLASH_SMEM>>>(q, k, v, mask, attn);

    tgemm_kernel<1, 0, 128><<<tg_grid(CM, CD, 128, 1), 256>>>(
        attn, Wo, bo, nullptr, xattn, CM, CD, CD, CD, CD, CD, 1, 0, 0, 0, 0, 0, 0);

    // ---- mamba ----
    tgemm_kernel<1, 0, 128><<<tg_grid(CM, 2 * CDI, 128, 1), 256>>>(
        x, in_proj_w, nullptr, nullptr, xz, CM, 2 * CDI, CD, CD, CD, 2 * CDI,
        1, 0, 0, 0, 0, 0, 0);

    {
        long long n = (long long)CM * CDI;
        conv_silu_kernel<<<(unsigned)((n + 255) / 256), 256>>>(xz, conv_w, conv_b, uact);
    }

    tgemm_kernel<1, 0, 128><<<tg_grid(CM, CR + 2 * CS, 128, 1), 256>>>(
        uact, x_proj_w, nullptr, nullptr, xdbc, CM, CR + 2 * CS, CDI,
        CDI, CDI, CR + 2 * CS, 1, 0, 0, 0, 0, 0, 0);

    tgemm_kernel<1, 2, 128><<<tg_grid(CM, CDI, 128, 1), 256>>>(
        xdbc, dt_proj_w, dt_proj_b, nullptr, delta, CM, CDI, CR,
        CR + 2 * CS, CR, CDI, 1, 0, 0, 0, 0, 0, 0);

    scan_kernel<<<(CB * CDI * 32) / 256, 256>>>(delta, uact, xdbc, xz, A_log, D_ssm, yss);

    tgemm_kernel<1, 0, 128><<<tg_grid(CM, CD, 128, 1), 256>>>(
        yss, out_proj_w, nullptr, nullptr, mamba, CM, CD, CDI, CDI, CDI, CD,
        1, 0, 0, 0, 0, 0, 0);

    // ---- residual + LN1 + LN2 ----
    add_ln_kernel<<<CM, 128>>>(x, xattn, mamba, ln1_g, ln1_b, ln2_g, ln2_b, h, hn);

    // ---- FFN ----
    tgemm_kernel<1, 1, 128><<<tg_grid(CM, CDFF, 128, 1), 256>>>(
        hn, ffn_w1, ffn_b1, nullptr, ff1, CM, CDFF, CD, CD, CD, CDFF,
        1, 0, 0, 0, 0, 0, 0);
    tgemm_kernel<1, 0, 128><<<tg_grid(CM, CD, 128, 1), 256>>>(
        ff1, ffn_w2, ffn_b2, h, out, CM, CD, CDFF, CDFF, CDFF, CD,
        1, 0, 0, 0, 0, 0, 0);
}

// round 11
// speedup vs baseline: 1.4262x; 1.0709x over previous
#include <cuda_runtime.h>
#include <math.h>

// ---------------- problem constants ----------------
#define CB   8
#define CD   512
#define CH   8
#define CE   64
#define CDI  1024
#define CS   64
#define CR   32
#define CKC  4
#define CDFF 2048
#define CL   1152          // T*W
#define CM   9216          // B*L

// ---------------- scratch ----------------
__device__ float g_q[CM * CD];
__device__ float g_k[CM * CD];
__device__ float g_v[CM * CD];
__device__ float g_attn[CM * CD];
__device__ float g_xattn[CM * CD];
__device__ float g_xz[CM * 2 * CDI];
__device__ float g_uact[CM * CDI];
__device__ float g_xdbc[CM * (CR + 2 * CS)];
__device__ float g_delta[CM * CDI];
__device__ float g_yss[CM * CDI];
__device__ float g_mamba[CM * CD];
__device__ float g_h[CM * CD];
__device__ float g_hn[CM * CD];
__device__ float g_ff1[CM * CDFF];

// ---------------- reductions ----------------
__device__ __forceinline__ float warpSum(float v) {
    #pragma unroll
    for (int o = 16; o; o >>= 1) v += __shfl_xor_sync(0xffffffffu, v, o);
    return v;
}
__device__ float blockSum(float v) {
    __shared__ float sh[32];
    int lane = threadIdx.x & 31, wid = threadIdx.x >> 5;
    v = warpSum(v);
    if (lane == 0) sh[wid] = v;
    __syncthreads();
    int nw = blockDim.x >> 5;
    v = (threadIdx.x < nw) ? sh[threadIdx.x] : 0.f;
    if (wid == 0) v = warpSum(v);
    if (threadIdx.x == 0) sh[0] = v;
    __syncthreads();
    float r = sh[0];
    __syncthreads();
    return r;
}

// ---------------- tf32 helpers ----------------
__device__ __forceinline__ unsigned f2tf(float f) {
    unsigned u;
    asm("cvt.rna.tf32.f32 %0, %1;" : "=r"(u) : "f"(f));
    return u;
}
__device__ __forceinline__ void mma8(float* c, const unsigned* a, const unsigned* b) {
    asm volatile("mma.sync.aligned.m16n8k8.row.col.f32.tf32.tf32.f32 "
                 "{%0,%1,%2,%3}, {%4,%5,%6,%7}, {%8,%9}, {%0,%1,%2,%3};\n"
                 : "+f"(c[0]), "+f"(c[1]), "+f"(c[2]), "+f"(c[3])
                 : "r"(a[0]), "r"(a[1]), "r"(a[2]), "r"(a[3]),
                   "r"(b[0]), "r"(b[1]));
}

// ================= tf32 GEMM: C[m,n] = epi(sum_k A[m,k]*B[n,k] + bias) + resid ======
// 128x128 tile, BK=16, double-buffered SMEM (ONE sync per k-tile), raw-fp32->tf32
// truncation (no cvt). M % 128 == 0, K % 16 == 0. N edges guarded.
// EPI: 0 none, 1 exact GELU, 2 softplus.
template <int EPI>
__global__ __launch_bounds__(256, 2)
void tgemm_kernel(const float* __restrict__ A, const float* __restrict__ Bm,
                  const float* __restrict__ bias, const float* __restrict__ resid,
                  float* __restrict__ C,
                  int M, int N, int K, int lda, int ldb, int ldc) {
    __shared__ float As[2][16][136];
    __shared__ float Bs[2][16][136];

    const int m0 = blockIdx.y * 128, n0 = blockIdx.x * 128;
    const int tid = threadIdx.x;
    const int lane = tid & 31, warp = tid >> 5;
    const int grp = lane >> 2, tig = lane & 3;
    const int wm0 = (warp & 3) * 32;
    const int wn0 = (warp >> 2) * 64;

    const int ar = tid >> 2;                 // 0..63
    const int akq = (tid & 3) * 4;           // 0,4,8,12
    const int aqx = (akq >> 2) << 3;         // swizzle xor

    float c[2][8][4];
    #pragma unroll
    for (int mi = 0; mi < 2; mi++)
        #pragma unroll
        for (int ni = 0; ni < 8; ni++)
            #pragma unroll
            for (int j = 0; j < 4; j++) c[mi][ni][j] = 0.f;

    float4 aR[2], bR[2];
    const float4 z4 = make_float4(0.f, 0.f, 0.f, 0.f);

    auto loadTiles = [&](int kt) {
        #pragma unroll
        for (int i = 0; i < 2; i++)
            aR[i] = *(const float4*)&A[(long long)(m0 + ar + i * 64) * lda + kt + akq];
        #pragma unroll
        for (int i = 0; i < 2; i++) {
            int bn = n0 + ar + i * 64;
            bR[i] = (bn < N) ? *(const float4*)&Bm[(long long)bn * ldb + kt + akq] : z4;
        }
    };
    auto storeTiles = [&](int p) {
        #pragma unroll
        for (int i = 0; i < 2; i++) {
            int m = (ar + i * 64) ^ aqx;
            As[p][akq + 0][m] = aR[i].x;
            As[p][akq + 1][m] = aR[i].y;
            As[p][akq + 2][m] = aR[i].z;
            As[p][akq + 3][m] = aR[i].w;
            Bs[p][akq + 0][m] = bR[i].x;
            Bs[p][akq + 1][m] = bR[i].y;
            Bs[p][akq + 2][m] = bR[i].z;
            Bs[p][akq + 3][m] = bR[i].w;
        }
    };

    const int nt = K / 16;
    loadTiles(0);
    storeTiles(0);
    if (nt > 1) loadTiles(16);

    for (int t = 0; t < nt; t++) {
        const int p = t & 1;
        __syncthreads();
        if (t + 1 < nt) storeTiles(p ^ 1);
        if (t + 2 < nt) loadTiles((t + 2) * 16);

        #pragma unroll
        for (int ks = 0; ks < 16; ks += 8) {
            const int xlo = (ks >> 2) << 3;
            const int xhi = xlo + 8;
            unsigned af[2][4];
            #pragma unroll
            for (int mi = 0; mi < 2; mi++) {
                int m = wm0 + mi * 16 + grp;
                af[mi][0] = __float_as_uint(As[p][ks + tig][m ^ xlo]);
                af[mi][1] = __float_as_uint(As[p][ks + tig][(m + 8) ^ xlo]);
                af[mi][2] = __float_as_uint(As[p][ks + tig + 4][m ^ xhi]);
                af[mi][3] = __float_as_uint(As[p][ks + tig + 4][(m + 8) ^ xhi]);
            }
            unsigned bf[8][2];
            #pragma unroll
            for (int ni = 0; ni < 8; ni++) {
                int n = wn0 + ni * 8 + grp;
                bf[ni][0] = __float_as_uint(Bs[p][ks + tig][n ^ xlo]);
                bf[ni][1] = __float_as_uint(Bs[p][ks + tig + 4][n ^ xhi]);
            }
            #pragma unroll
            for (int mi = 0; mi < 2; mi++)
                #pragma unroll
                for (int ni = 0; ni < 8; ni++)
                    mma8(c[mi][ni], af[mi], bf[ni]);
        }
    }

    #pragma unroll
    for (int mi = 0; mi < 2; mi++) {
        int r0 = m0 + wm0 + mi * 16 + grp;
        #pragma unroll
        for (int ni = 0; ni < 8; ni++) {
            int col = n0 + wn0 + ni * 8 + 2 * tig;
            if (col >= N) continue;
            float bx = 0.f, by = 0.f;
            if (bias) { bx = bias[col]; by = bias[col + 1]; }
            float v0 = c[mi][ni][0] + bx, v1 = c[mi][ni][1] + by;
            float v2 = c[mi][ni][2] + bx, v3 = c[mi][ni][3] + by;
            if (EPI == 1) {
                v0 = 0.5f * v0 * (1.f + erff(v0 * 0.70710678118654752f));
                v1 = 0.5f * v1 * (1.f + erff(v1 * 0.70710678118654752f));
                v2 = 0.5f * v2 * (1.f + erff(v2 * 0.70710678118654752f));
                v3 = 0.5f * v3 * (1.f + erff(v3 * 0.70710678118654752f));
            } else if (EPI == 2) {
                v0 = (v0 > 20.f) ? v0 : log1pf(__expf(v0));
                v1 = (v1 > 20.f) ? v1 : log1pf(__expf(v1));
                v2 = (v2 > 20.f) ? v2 : log1pf(__expf(v2));
                v3 = (v3 > 20.f) ? v3 : log1pf(__expf(v3));
            }
            if (resid) {
                float2 ra = *(const float2*)&resid[(long long)r0 * ldc + col];
                float2 rb = *(const float2*)&resid[(long long)(r0 + 8) * ldc + col];
                v0 += ra.x; v1 += ra.y; v2 += rb.x; v3 += rb.y;
            }
            *(float2*)&C[(long long)r0 * ldc + col] = make_float2(v0, v1);
            *(float2*)&C[(long long)(r0 + 8) * ldc + col] = make_float2(v2, v3);
        }
    }
}

// ================= flash attention (512 threads / 16 warps) =================
// grid (9, 64): x = q-tile (128 rows), y = b*8+h.
// S phase: 4x4 warp grid, 32x32 per warp. PV phase: 8x2 warp grid, 16x32 per warp.
#define QS_N  (64 * 136)
#define VT_ST 133
#define PS_ST 134
__global__ __launch_bounds__(512, 1)
void flash_kernel(const float* __restrict__ qg, const float* __restrict__ kg,
                  const float* __restrict__ vg, const unsigned char* __restrict__ maskg,
                  float* __restrict__ og) {
    extern __shared__ float smf[];
    unsigned* Qs = (unsigned*)smf;                   // [64][136]
    unsigned* Ks = (unsigned*)(smf + QS_N);          // [64][136]
    float* Vt = smf + 2 * QS_N;                      // [64][133]
    float* Ps = Vt + 64 * VT_ST;                     // [128][134]
    float* sm_m  = Ps + 128 * PS_ST;                 // 128
    float* sm_l  = sm_m + 128;                       // 128
    float* sm_al = sm_l + 128;                       // 128
    float* pmax  = sm_al + 128;                      // [4][128]
    float* psum  = pmax + 512;                       // [4][128]
    unsigned char* msk = (unsigned char*)(psum + 512);  // 128 bytes

    const int tid = threadIdx.x;
    const int lane = tid & 31, warp = tid >> 5;      // warp 0..15
    const int grp = lane >> 2, tig = lane & 3;
    const int wm  = (warp & 3) * 32;                 // S: m-block
    const int wn  = (warp >> 2) * 32;                // S: n-block
    const int wc  = warp >> 2;                       // S: column slab 0..3
    const int wmP = (warp & 7) * 16;                 // PV: m-block
    const int wnP = (warp >> 3) * 32;                // PV: n-block (e)

    const int q0 = blockIdx.x * 128;
    const int b = blockIdx.y >> 3, h = blockIdx.y & 7;
    const long long bL = (long long)b * CL;
    const float* qbase = qg + (bL + q0) * CD + h * 64;
    const float* kbase = kg + bL * CD + h * 64;
    const float* vbase = vg + bL * CD + h * 64;
    const unsigned char* mbase = maskg + bL;

    if (tid < 128) { sm_m[tid] = -INFINITY; sm_l[tid] = 0.f; }

    // ---- stage Q (scaled, tf32) into Qs[k][m^swz]: 512 threads, 1 row each ----
    const int r_ld = tid >> 2;                       // 0..127
    const int akq = (tid & 3) * 4;
    const int aqx = (tid & 3) << 3;
    #pragma unroll
    for (int kt2 = 0; kt2 < 4; kt2++) {
        float4 v4 = *(const float4*)&qbase[(long long)r_ld * CD + kt2 * 16 + akq];
        int col = r_ld ^ aqx;
        int kb = kt2 * 16 + akq;
        Qs[(kb + 0) * 136 + col] = f2tf(v4.x * 0.125f);
        Qs[(kb + 1) * 136 + col] = f2tf(v4.y * 0.125f);
        Qs[(kb + 2) * 136 + col] = f2tf(v4.z * 0.125f);
        Qs[(kb + 3) * 136 + col] = f2tf(v4.w * 0.125f);
    }

    float o[4][4];
    #pragma unroll
    for (int ni = 0; ni < 4; ni++)
        #pragma unroll
        for (int j = 0; j < 4; j++) o[ni][j] = 0.f;

    const int ve = tid & 63, vsb = (tid >> 6) * 16;

    for (int it = 0; it < 9; it++) {
        const int s0 = it * 128;
        __syncthreads();   // protect Ks/Vt/msk vs prev PV reads

        // ---- load K tile -> Ks[k][n^swz] ----
        #pragma unroll
        for (int kt2 = 0; kt2 < 4; kt2++) {
            float4 v4 = *(const float4*)&kbase[(long long)(s0 + r_ld) * CD + kt2 * 16 + akq];
            int col = r_ld ^ aqx;
            int kb = kt2 * 16 + akq;
            Ks[(kb + 0) * 136 + col] = f2tf(v4.x);
            Ks[(kb + 1) * 136 + col] = f2tf(v4.y);
            Ks[(kb + 2) * 136 + col] = f2tf(v4.z);
            Ks[(kb + 3) * 136 + col] = f2tf(v4.w);
        }
        // ---- load V tile transposed -> Vt[e][s] ----
        #pragma unroll 4
        for (int i = 0; i < 16; i++) {
            int s = vsb + i;
            float v = vbase[(long long)(s0 + s) * CD + ve];
            Vt[ve * VT_ST + s] = __uint_as_float(f2tf(v));
        }
        if (tid < 128) msk[tid] = mbase[s0 + tid];
        __syncthreads();

        // ---- S = Q K^T: per-warp 32x32, K=64 ----
        float c[2][4][4];
        #pragma unroll
        for (int mi = 0; mi < 2; mi++)
            #pragma unroll
            for (int ni = 0; ni < 4; ni++)
                #pragma unroll
                for (int j = 0; j < 4; j++) c[mi][ni][j] = 0.f;
        #pragma unroll
        for (int ks = 0; ks < 64; ks += 8) {
            const int xlo = ((ks >> 2) & 3) << 3;
            const int xhi = (((ks + 4) >> 2) & 3) << 3;
            unsigned af[2][4];
            #pragma unroll
            for (int mi = 0; mi < 2; mi++) {
                int m = wm + mi * 16 + grp;
                af[mi][0] = Qs[(ks + tig) * 136 + (m ^ xlo)];
                af[mi][1] = Qs[(ks + tig) * 136 + ((m + 8) ^ xlo)];
                af[mi][2] = Qs[(ks + tig + 4) * 136 + (m ^ xhi)];
                af[mi][3] = Qs[(ks + tig + 4) * 136 + ((m + 8) ^ xhi)];
            }
            unsigned bf[4][2];
            #pragma unroll
            for (int ni = 0; ni < 4; ni++) {
                int n = wn + ni * 8 + grp;
                bf[ni][0] = Ks[(ks + tig) * 136 + (n ^ xlo)];
                bf[ni][1] = Ks[(ks + tig + 4) * 136 + (n ^ xhi)];
            }
            #pragma unroll
            for (int mi = 0; mi < 2; mi++)
                #pragma unroll
                for (int ni = 0; ni < 4; ni++)
                    mma8(c[mi][ni], af[mi], bf[ni]);
        }

        // ---- per-row tile max (mask applied) ----
        #pragma unroll
        for (int mi = 0; mi < 2; mi++) {
            #pragma unroll
            for (int p = 0; p < 2; p++) {
                float tm = -INFINITY;
                #pragma unroll
                for (int ni = 0; ni < 4; ni++) {
                    int col = wn + ni * 8 + 2 * tig;
                    float a = msk[col] ? -INFINITY : c[mi][ni][2 * p];
                    float bb = msk[col + 1] ? -INFINITY : c[mi][ni][2 * p + 1];
                    tm = fmaxf(tm, fmaxf(a, bb));
                }
                tm = fmaxf(tm, __shfl_xor_sync(0xffffffffu, tm, 1));
                tm = fmaxf(tm, __shfl_xor_sync(0xffffffffu, tm, 2));
                if (tig == 0) pmax[wc * 128 + wm + mi * 16 + grp + 8 * p] = tm;
            }
        }
        __syncthreads();

        if (tid < 128) {
            float mo = sm_m[tid];
            float nm = fmaxf(fmaxf(mo, fmaxf(pmax[tid], pmax[128 + tid])),
                             fmaxf(pmax[256 + tid], pmax[384 + tid]));
            float al = (nm == -INFINITY) ? 1.f : __expf(mo - nm);
            sm_al[tid] = al;
            sm_m[tid] = nm;
        }
        __syncthreads();

        // ---- exp, store P, row sums ----
        #pragma unroll
        for (int mi = 0; mi < 2; mi++) {
            #pragma unroll
            for (int p = 0; p < 2; p++) {
                int row = wm + mi * 16 + grp + 8 * p;
                float nm = sm_m[row];
                float rs = 0.f;
                #pragma unroll
                for (int ni = 0; ni < 4; ni++) {
                    int col = wn + ni * 8 + 2 * tig;
                    float e0 = msk[col]     ? 0.f : __expf(c[mi][ni][2 * p] - nm);
                    float e1 = msk[col + 1] ? 0.f : __expf(c[mi][ni][2 * p + 1] - nm);
                    rs += e0 + e1;
                    *(float2*)&Ps[row * PS_ST + col] = make_float2(e0, e1);
                }
                rs += __shfl_xor_sync(0xffffffffu, rs, 1);
                rs += __shfl_xor_sync(0xffffffffu, rs, 2);
                if (tig == 0) psum[wc * 128 + row] = rs;
            }
        }
        __syncthreads();

        // ---- rescale O, update l, PV mma (per-warp 16x32) ----
        {
            float al0 = sm_al[wmP + grp];
            float al1 = sm_al[wmP + grp + 8];
            #pragma unroll
            for (int ni = 0; ni < 4; ni++) {
                o[ni][0] *= al0; o[ni][1] *= al0;
                o[ni][2] *= al1; o[ni][3] *= al1;
            }
        }
        if (tid < 128)
            sm_l[tid] = sm_l[tid] * sm_al[tid]
                      + psum[tid] + psum[128 + tid] + psum[256 + tid] + psum[384 + tid];

        const float* pr0 = Ps + (wmP + grp) * PS_ST;
        const float* pr1 = Ps + (wmP + grp + 8) * PS_ST;
        #pragma unroll
        for (int ks = 0; ks < 128; ks += 8) {
            unsigned ap[4];
            ap[0] = __float_as_uint(pr0[ks + tig]);
            ap[1] = __float_as_uint(pr1[ks + tig]);
            ap[2] = __float_as_uint(pr0[ks + tig + 4]);
            ap[3] = __float_as_uint(pr1[ks + tig + 4]);
            #pragma unroll
            for (int ni = 0; ni < 4; ni++) {
                unsigned bv[2];
                const float* vr = Vt + (wnP + ni * 8 + grp) * VT_ST;
                bv[0] = __float_as_uint(vr[ks + tig]);
                bv[1] = __float_as_uint(vr[ks + tig + 4]);
                mma8(o[ni], ap, bv);
            }
        }
    }
    __syncthreads();

    // ---- normalize + write ----
    {
        int r0 = wmP + grp, r1 = r0 + 8;
        float il0 = 1.f / sm_l[r0];
        float il1 = 1.f / sm_l[r1];
        float* o0 = og + (bL + q0 + r0) * CD + h * 64;
        float* o1 = og + (bL + q0 + r1) * CD + h * 64;
        #pragma unroll
        for (int ni = 0; ni < 4; ni++) {
            int col = wnP + ni * 8 + 2 * tig;
            *(float2*)&o0[col] = make_float2(o[ni][0] * il0, o[ni][1] * il0);
            *(float2*)&o1[col] = make_float2(o[ni][2] * il1, o[ni][3] * il1);
        }
    }
}

// ---------------- conv + SiLU ----------------
__global__ void conv_silu_kernel(const float* __restrict__ xz, const float* __restrict__ cw,
                                 const float* __restrict__ cb, float* __restrict__ uact) {
    long long idx = (long long)blockIdx.x * blockDim.x + threadIdx.x;
    if (idx >= (long long)CM * CDI) return;
    int di = (int)(idx % CDI);
    long long bl = idx / CDI;
    int t = (int)(bl % CL);
    long long bbase = bl - t;
    float acc = cb[di];
    #pragma unroll
    for (int kk = 0; kk < CKC; kk++) {
        int t2 = t + kk - (CKC - 1);
        if (t2 >= 0)
            acc = fmaf(xz[(bbase + t2) * (long long)(2 * CDI) + di], cw[di * CKC + kk], acc);
    }
    float sg = 1.f / (1.f + __expf(-acc));
    uact[idx] = acc * sg;
}

// ---------------- selective scan ----------------
__global__ void scan_kernel(const float* __restrict__ delta, const float* __restrict__ uact,
                            const float* __restrict__ xdbc, const float* __restrict__ xz,
                            const float* __restrict__ A_log, const float* __restrict__ D_ssm,
                            float* __restrict__ y) {
    int wg = (int)(((long long)blockIdx.x * blockDim.x + threadIdx.x) >> 5);
    int lane = threadIdx.x & 31;
    if (wg >= CB * CDI) return;
    int b = wg >> 10;
    int di = wg & (CDI - 1);

    float a0 = -__expf(A_log[di * CS + lane]);
    float a1 = -__expf(A_log[di * CS + lane + 32]);
    float Dd = D_ssm[di];
    float h0 = 0.f, h1 = 0.f;

    const float* dptr = delta + (long long)b * CL * CDI + di;
    const float* uptr = uact + (long long)b * CL * CDI + di;
    const float* zptr = xz + (long long)b * CL * (2 * CDI) + CDI + di;
    const float* bc = xdbc + (long long)b * CL * (CR + 2 * CS);
    float* yptr = y + (long long)b * CL * CDI + di;

    for (int t = 0; t < CL; t++) {
        float dt = dptr[(long long)t * CDI];
        float uu = uptr[(long long)t * CDI];
        const float* xrow = bc + (long long)t * (CR + 2 * CS);
        float B0 = xrow[CR + lane];
        float B1 = xrow[CR + 32 + lane];
        float C0 = xrow[CR + CS + lane];
        float C1 = xrow[CR + CS + 32 + lane];
        float dA0 = __expf(dt * a0);
        float dA1 = __expf(dt * a1);
        float du = dt * uu;
        h0 = fmaf(h0, dA0, du * B0);
        h1 = fmaf(h1, dA1, du * B1);
        float acc = fmaf(h0, C0, h1 * C1);
        #pragma unroll
        for (int o = 16; o; o >>= 1) acc += __shfl_down_sync(0xffffffffu, acc, o);
        if (lane == 0) {
            float zv = zptr[(long long)t * (2 * CDI)];
            float sz = zv / (1.f + __expf(-zv));
            yptr[(long long)t * CDI] = (acc + uu * Dd) * sz;
        }
    }
}

// ---------------- residual add3 + LN1 + LN2 ----------------
__global__ void add_ln_kernel(const float* __restrict__ x, const float* __restrict__ attn,
                              const float* __restrict__ mamba,
                              const float* __restrict__ g1, const float* __restrict__ b1,
                              const float* __restrict__ g2, const float* __restrict__ b2,
                              float* __restrict__ hout, float* __restrict__ hnout) {
    long long row = blockIdx.x;
    const long long base = row * CD;
    float s[4];
    #pragma unroll
    for (int i = 0; i < 4; i++) {
        int c = threadIdx.x + i * 128;
        s[i] = x[base + c] + attn[base + c] + mamba[base + c];
    }
    float sum = s[0] + s[1] + s[2] + s[3];
    float mean = blockSum(sum) * (1.f / CD);
    float vs = 0.f;
    #pragma unroll
    for (int i = 0; i < 4; i++) { float d = s[i] - mean; vs += d * d; }
    float var = blockSum(vs) * (1.f / CD);
    float inv = rsqrtf(var + 1e-5f);
    float h[4];
    #pragma unroll
    for (int i = 0; i < 4; i++) {
        int c = threadIdx.x + i * 128;
        h[i] = (s[i] - mean) * inv * g1[c] + b1[c];
        hout[base + c] = h[i];
    }
    float sum2 = h[0] + h[1] + h[2] + h[3];
    float mean2 = blockSum(sum2) * (1.f / CD);
    float vs2 = 0.f;
    #pragma unroll
    for (int i = 0; i < 4; i++) { float d = h[i] - mean2; vs2 += d * d; }
    float var2 = blockSum(vs2) * (1.f / CD);
    float inv2 = rsqrtf(var2 + 1e-6f);
    #pragma unroll
    for (int i = 0; i < 4; i++) {
        int c = threadIdx.x + i * 128;
        hnout[base + c] = (h[i] - mean2) * inv2 * g2[c] + b2[c];
    }
}

// ---------------- host ----------------
static inline dim3 tg_grid(int M, int N) {
    return dim3((N + 127) / 128, (M + 127) / 128);
}

extern "C" void kernel_launch(void* const* d_in, const int* in_sizes, int n_in,
                              void* d_out, int out_size) {
    const float* x          = (const float*)d_in[0];
    const unsigned char* mask = (const unsigned char*)d_in[1];
    const float* Wq = (const float*)d_in[2];
    const float* bq = (const float*)d_in[3];
    const float* Wk = (const float*)d_in[4];
    const float* bk = (const float*)d_in[5];
    const float* Wv = (const float*)d_in[6];
    const float* bv = (const float*)d_in[7];
    const float* Wo = (const float*)d_in[8];
    const float* bo = (const float*)d_in[9];
    const float* in_proj_w = (const float*)d_in[10];
    const float* conv_w    = (const float*)d_in[11];
    const float* conv_b    = (const float*)d_in[12];
    const float* x_proj_w  = (const float*)d_in[13];
    const float* dt_proj_w = (const float*)d_in[14];
    const float* dt_proj_b = (const float*)d_in[15];
    const float* A_log     = (const float*)d_in[16];
    const float* D_ssm     = (const float*)d_in[17];
    const float* out_proj_w = (const float*)d_in[18];
    const float* ln1_g = (const float*)d_in[19];
    const float* ln1_b = (const float*)d_in[20];
    const float* ffn_w1 = (const float*)d_in[21];
    const float* ffn_b1 = (const float*)d_in[22];
    const float* ffn_w2 = (const float*)d_in[23];
    const float* ffn_b2 = (const float*)d_in[24];
    const float* ln2_g = (const float*)d_in[25];
    const float* ln2_b = (const float*)d_in[26];
    float* out = (float*)d_out;

    float *q, *k, *v, *attn, *xattn, *xz, *uact, *xdbc, *delta, *yss, *mamba, *h, *hn, *ff1;
    cudaGetSymbolAddress((void**)&q, g_q);
    cudaGetSymbolAddress((void**)&k, g_k);
    cudaGetSymbolAddress((void**)&v, g_v);
    cudaGetSymbolAddress((void**)&attn, g_attn);
    cudaGetSymbolAddress((void**)&xattn, g_xattn);
    cudaGetSymbolAddress((void**)&xz, g_xz);
    cudaGetSymbolAddress((void**)&uact, g_uact);
    cudaGetSymbolAddress((void**)&xdbc, g_xdbc);
    cudaGetSymbolAddress((void**)&delta, g_delta);
    cudaGetSymbolAddress((void**)&yss, g_yss);
    cudaGetSymbolAddress((void**)&mamba, g_mamba);
    cudaGetSymbolAddress((void**)&h, g_h);
    cudaGetSymbolAddress((void**)&hn, g_hn);
    cudaGetSymbolAddress((void**)&ff1, g_ff1);

    // flash smem: Qs+Ks (2*8704) + Vt (64*133=8512) + Ps (128*134=17152)
    //           + sm_m/sm_l/sm_al (384) + pmax/psum (1024) + mask (32)
    const int FLASH_SMEM = (2 * QS_N + 64 * VT_ST + 128 * PS_ST + 384 + 1024 + 32) * 4;
    cudaFuncSetAttribute(flash_kernel, cudaFuncAttributeMaxDynamicSharedMemorySize, FLASH_SMEM);

    // ---- attention ----
    tgemm_kernel<0><<<tg_grid(CM, CD), 256>>>(x, Wq, bq, nullptr, q, CM, CD, CD, CD, CD, CD);
    tgemm_kernel<0><<<tg_grid(CM, CD), 256>>>(x, Wk, bk, nullptr, k, CM, CD, CD, CD, CD, CD);
    tgemm_kernel<0><<<tg_grid(CM, CD), 256>>>(x, Wv, bv, nullptr, v, CM, CD, CD, CD, CD, CD);

    flash_kernel<<<dim3(CL / 128, CB * CH), 512, FLASH_SMEM>>>(q, k, v, mask, attn);

    tgemm_kernel<0><<<tg_grid(CM, CD), 256>>>(attn, Wo, bo, nullptr, xattn, CM, CD, CD, CD, CD, CD);

    // ---- mamba ----
    tgemm_kernel<0><<<tg_grid(CM, 2 * CDI), 256>>>(
        x, in_proj_w, nullptr, nullptr, xz, CM, 2 * CDI, CD, CD, CD, 2 * CDI);

    {
        long long n = (long long)CM * CDI;
        conv_silu_kernel<<<(unsigned)((n + 255) / 256), 256>>>(xz, conv_w, conv_b, uact);
    }

    tgemm_kernel<0><<<tg_grid(CM, CR + 2 * CS), 256>>>(
        uact, x_proj_w, nullptr, nullptr, xdbc, CM, CR + 2 * CS, CDI, CDI, CDI, CR + 2 * CS);

    tgemm_kernel<2><<<tg_grid(CM, CDI), 256>>>(
        xdbc, dt_proj_w, dt_proj_b, nullptr, delta, CM, CDI, CR, CR + 2 * CS, CR, CDI);

    scan_kernel<<<(CB * CDI * 32) / 256, 256>>>(delta, uact, xdbc, xz, A_log, D_ssm, yss);

    tgemm_kernel<0><<<tg_grid(CM, CD), 256>>>(
        yss, out_proj_w, nullptr, nullptr, mamba, CM, CD, CDI, CDI, CDI, CD);

    // ---- residual + LN1 + LN2 ----
    add_ln_kernel<<<CM, 128>>>(x, xattn, mamba, ln1_g, ln1_b, ln2_g, ln2_b, h, hn);

    // ---- FFN ----
    tgemm_kernel<1><<<tg_grid(CM, CDFF), 256>>>(
        hn, ffn_w1, ffn_b1, nullptr, ff1, CM, CDFF, CD, CD, CD, CDFF);
    tgemm_kernel<0><<<tg_grid(CM, CD), 256>>>(
        ff1, ffn_w2, ffn_b2, h, out, CM, CD, CDFF, CDFF, CDFF, CD);
}